// round 1
// baseline (speedup 1.0000x reference)
#include <cuda_runtime.h>
#include <cstdint>

#define BB 16
#define PP 2048
#define HH 2048
#define DD 1024

// 256 MiB scratch for S / probs (B*P*H fp32). Static __device__ global: the
// allowed scratch mechanism (no runtime allocation).
__device__ float g_S[(size_t)BB * PP * HH];

__device__ __forceinline__ float to_tf32(float x) {
    uint32_t u;
    asm("cvt.rna.tf32.f32 %0, %1;" : "=r"(u) : "f"(x));
    return __uint_as_float(u);
}

__device__ __forceinline__ void mma_tf32(float c[4], const uint32_t a[4], const uint32_t b[2]) {
    asm volatile(
        "mma.sync.aligned.m16n8k8.row.col.f32.tf32.tf32.f32 "
        "{%0,%1,%2,%3}, {%4,%5,%6,%7}, {%8,%9}, {%0,%1,%2,%3};\n"
        : "+f"(c[0]), "+f"(c[1]), "+f"(c[2]), "+f"(c[3])
        : "r"(a[0]), "r"(a[1]), "r"(a[2]), "r"(a[3]), "r"(b[0]), "r"(b[1]));
}

// ---------------------------------------------------------------------------
// Kernel 1: S[b, p, h] = sum_d Q[b,p,d] * K[b,h,d]   (no scale; applied later)
// CTA tile 128(p) x 128(h), k-chunk 32 over D. 256 threads, 8 warps (2x4),
// each warp 64x32 via 4x4 grid of m16n8k8 tf32 MMAs.
// ---------------------------------------------------------------------------
__global__ __launch_bounds__(256) void qk_kernel(const float* __restrict__ Q,
                                                 const float* __restrict__ K) {
    __shared__ float As[32][132];
    __shared__ float Bs[32][132];

    const int b = blockIdx.z, pt = blockIdx.y, ht = blockIdx.x;
    const float* Qb = Q + ((size_t)(b * PP + pt * 128)) * DD;
    const float* Kb = K + ((size_t)(b * HH + ht * 128)) * DD;

    const int tid = threadIdx.x;
    const int lane = tid & 31, wid = tid >> 5;
    const int g = lane >> 2, tg = lane & 3;
    const int wm = wid >> 2, wn = wid & 3;   // wm 0..1 (64 rows), wn 0..3 (32 cols)

    float acc[4][4][4];
#pragma unroll
    for (int mt = 0; mt < 4; mt++)
#pragma unroll
        for (int nt = 0; nt < 4; nt++)
#pragma unroll
            for (int i = 0; i < 4; i++) acc[mt][nt][i] = 0.0f;

    const int srow = tid >> 1;      // 0..127 staging row
    const int shalf = tid & 1;      // which 16-wide half of the 32 k-chunk

    for (int kc = 0; kc < DD; kc += 32) {
        const float4* q4 = (const float4*)(Qb + (size_t)srow * DD + kc + shalf * 16);
        const float4* k4 = (const float4*)(Kb + (size_t)srow * DD + kc + shalf * 16);
#pragma unroll
        for (int i = 0; i < 4; i++) {
            float4 v = q4[i];
            int d0 = shalf * 16 + i * 4;
            As[d0 + 0][srow] = to_tf32(v.x);
            As[d0 + 1][srow] = to_tf32(v.y);
            As[d0 + 2][srow] = to_tf32(v.z);
            As[d0 + 3][srow] = to_tf32(v.w);
            float4 w = k4[i];
            Bs[d0 + 0][srow] = to_tf32(w.x);
            Bs[d0 + 1][srow] = to_tf32(w.y);
            Bs[d0 + 2][srow] = to_tf32(w.z);
            Bs[d0 + 3][srow] = to_tf32(w.w);
        }
        __syncthreads();

#pragma unroll
        for (int kk = 0; kk < 32; kk += 8) {
            uint32_t a[4][4], bf[4][2];
#pragma unroll
            for (int mt = 0; mt < 4; mt++) {
                int r0 = wm * 64 + mt * 16;
                a[mt][0] = __float_as_uint(As[kk + tg][r0 + g]);
                a[mt][1] = __float_as_uint(As[kk + tg][r0 + g + 8]);
                a[mt][2] = __float_as_uint(As[kk + tg + 4][r0 + g]);
                a[mt][3] = __float_as_uint(As[kk + tg + 4][r0 + g + 8]);
            }
#pragma unroll
            for (int nt = 0; nt < 4; nt++) {
                int c0 = wn * 32 + nt * 8;
                bf[nt][0] = __float_as_uint(Bs[kk + tg][c0 + g]);
                bf[nt][1] = __float_as_uint(Bs[kk + tg + 4][c0 + g]);
            }
#pragma unroll
            for (int mt = 0; mt < 4; mt++)
#pragma unroll
                for (int nt = 0; nt < 4; nt++) mma_tf32(acc[mt][nt], a[mt], bf[nt]);
        }
        __syncthreads();
    }

    const size_t rbase = (size_t)b * PP + pt * 128;
#pragma unroll
    for (int mt = 0; mt < 4; mt++) {
        int r0 = wm * 64 + mt * 16 + g;
#pragma unroll
        for (int nt = 0; nt < 4; nt++) {
            int c = ht * 128 + wn * 32 + nt * 8 + tg * 2;
            float* p0 = &g_S[(rbase + r0) * HH + c];
            p0[0] = acc[mt][nt][0];
            p0[1] = acc[mt][nt][1];
            float* p1 = &g_S[(rbase + r0 + 8) * HH + c];
            p1[0] = acc[mt][nt][2];
            p1[1] = acc[mt][nt][3];
        }
    }
}

// ---------------------------------------------------------------------------
// Kernel 2: masked softmax per (b, p) row, in place on g_S.
// Equivalent to reference's softmax(sim*mask)*mask renormalized.
// ---------------------------------------------------------------------------
__global__ __launch_bounds__(256) void softmax_kernel(const float* __restrict__ hmask) {
    const int rowid = blockIdx.x;       // 0 .. B*P-1
    const int b = rowid >> 11;          // / 2048
    float* s = g_S + (size_t)rowid * HH;
    const float* hm = hmask + (size_t)b * HH;
    const int tid = threadIdx.x;

    float v[8];
    float mk[8];
    float lmax = -1e30f;
#pragma unroll
    for (int i = 0; i < 8; i++) {
        int h = i * 256 + tid;
        v[i] = s[h] * 0.03125f;   // 1/sqrt(1024)
        mk[i] = hm[h];
        if (mk[i] != 0.0f) lmax = fmaxf(lmax, v[i]);
    }

    __shared__ float redm[8];
    __shared__ float reds[8];
#pragma unroll
    for (int o = 16; o > 0; o >>= 1) lmax = fmaxf(lmax, __shfl_xor_sync(0xFFFFFFFFu, lmax, o));
    if ((tid & 31) == 0) redm[tid >> 5] = lmax;
    __syncthreads();
    float M = fmaxf(fmaxf(fmaxf(redm[0], redm[1]), fmaxf(redm[2], redm[3])),
                    fmaxf(fmaxf(redm[4], redm[5]), fmaxf(redm[6], redm[7])));

    float lsum = 0.0f;
#pragma unroll
    for (int i = 0; i < 8; i++) {
        v[i] = (mk[i] != 0.0f) ? __expf(v[i] - M) : 0.0f;
        lsum += v[i];
    }
#pragma unroll
    for (int o = 16; o > 0; o >>= 1) lsum += __shfl_xor_sync(0xFFFFFFFFu, lsum, o);
    if ((tid & 31) == 0) reds[tid >> 5] = lsum;
    __syncthreads();
    float T = reds[0] + reds[1] + reds[2] + reds[3] + reds[4] + reds[5] + reds[6] + reds[7];
    float inv = 1.0f / T;
#pragma unroll
    for (int i = 0; i < 8; i++) s[i * 256 + tid] = v[i] * inv;
}

// ---------------------------------------------------------------------------
// Kernel 3: out[b,p,d] = (sum_h P[b,p,h] * V[b,h,d]) * pmask[b,p]
// Same tiling as kernel 1; k-dim is H (2048), B operand (V) staged directly.
// ---------------------------------------------------------------------------
__global__ __launch_bounds__(256) void pv_kernel(const float* __restrict__ V,
                                                 const float* __restrict__ pmask,
                                                 float* __restrict__ out) {
    __shared__ float As[32][132];
    __shared__ float Bs[32][132];

    const int b = blockIdx.z, pt = blockIdx.y, dt = blockIdx.x;   // dt 0..7
    const float* Pb = g_S + ((size_t)(b * PP + pt * 128)) * HH;
    const float* Vb = V + (size_t)b * HH * DD + dt * 128;

    const int tid = threadIdx.x;
    const int lane = tid & 31, wid = tid >> 5;
    const int g = lane >> 2, tg = lane & 3;
    const int wm = wid >> 2, wn = wid & 3;

    float acc[4][4][4];
#pragma unroll
    for (int mt = 0; mt < 4; mt++)
#pragma unroll
        for (int nt = 0; nt < 4; nt++)
#pragma unroll
            for (int i = 0; i < 4; i++) acc[mt][nt][i] = 0.0f;

    const int prow = tid >> 1, phalf = tid & 1;   // P staging: 128 rows, 2 thr/row
    const int vrow = tid >> 3, vseg = tid & 7;    // V staging: 32 rows, 8 thr/row

    for (int hc = 0; hc < HH; hc += 32) {
        const float4* p4 = (const float4*)(Pb + (size_t)prow * HH + hc + phalf * 16);
#pragma unroll
        for (int i = 0; i < 4; i++) {
            float4 v = p4[i];
            int k0 = phalf * 16 + i * 4;
            As[k0 + 0][prow] = to_tf32(v.x);
            As[k0 + 1][prow] = to_tf32(v.y);
            As[k0 + 2][prow] = to_tf32(v.z);
            As[k0 + 3][prow] = to_tf32(v.w);
        }
        const float4* v4 = (const float4*)(Vb + (size_t)(hc + vrow) * DD + vseg * 16);
#pragma unroll
        for (int i = 0; i < 4; i++) {
            float4 v = v4[i];
            float4 t;
            t.x = to_tf32(v.x);
            t.y = to_tf32(v.y);
            t.z = to_tf32(v.z);
            t.w = to_tf32(v.w);
            *(float4*)&Bs[vrow][vseg * 16 + i * 4] = t;
        }
        __syncthreads();

#pragma unroll
        for (int kk = 0; kk < 32; kk += 8) {
            uint32_t a[4][4], bf[4][2];
#pragma unroll
            for (int mt = 0; mt < 4; mt++) {
                int r0 = wm * 64 + mt * 16;
                a[mt][0] = __float_as_uint(As[kk + tg][r0 + g]);
                a[mt][1] = __float_as_uint(As[kk + tg][r0 + g + 8]);
                a[mt][2] = __float_as_uint(As[kk + tg + 4][r0 + g]);
                a[mt][3] = __float_as_uint(As[kk + tg + 4][r0 + g + 8]);
            }
#pragma unroll
            for (int nt = 0; nt < 4; nt++) {
                int c0 = wn * 32 + nt * 8;
                bf[nt][0] = __float_as_uint(Bs[kk + tg][c0 + g]);
                bf[nt][1] = __float_as_uint(Bs[kk + tg + 4][c0 + g]);
            }
#pragma unroll
            for (int mt = 0; mt < 4; mt++)
#pragma unroll
                for (int nt = 0; nt < 4; nt++) mma_tf32(acc[mt][nt], a[mt], bf[nt]);
        }
        __syncthreads();
    }

#pragma unroll
    for (int mt = 0; mt < 4; mt++) {
        int rg = pt * 128 + wm * 64 + mt * 16 + g;
        float m0 = pmask[(size_t)b * PP + rg];
        float m1 = pmask[(size_t)b * PP + rg + 8];
#pragma unroll
        for (int nt = 0; nt < 4; nt++) {
            int c = dt * 128 + wn * 32 + nt * 8 + tg * 2;
            float* o0 = out + ((size_t)b * PP + rg) * DD + c;
            o0[0] = acc[mt][nt][0] * m0;
            o0[1] = acc[mt][nt][1] * m0;
            float* o1 = out + ((size_t)b * PP + rg + 8) * DD + c;
            o1[0] = acc[mt][nt][2] * m1;
            o1[1] = acc[mt][nt][3] * m1;
        }
    }
}

extern "C" void kernel_launch(void* const* d_in, const int* in_sizes, int n_in,
                              void* d_out, int out_size) {
    const float* Q     = (const float*)d_in[0];  // premise_batch  [B,P,D]
    const float* pmask = (const float*)d_in[1];  // premise_mask   [B,P]
    const float* V     = (const float*)d_in[2];  // hypothesis_batch [B,H,D]
    const float* hmask = (const float*)d_in[3];  // hypothesis_mask  [B,H]
    float* out = (float*)d_out;

    qk_kernel<<<dim3(16, 16, 16), 256>>>(Q, V);
    softmax_kernel<<<BB * PP, 256>>>(hmask);
    pv_kernel<<<dim3(8, 16, 16), 256>>>(V, pmask, out);
}

// round 3
// speedup vs baseline: 1.9474x; 1.9474x over previous
#include <cuda_runtime.h>
#include <cstdint>

#define BB 16
#define PP 2048
#define HB 2048
#define DB 1024

// ---- device scratch (static __device__ globals: the allowed mechanism) ----
__device__ float g_E[(size_t)BB * PP * HB];      // 256 MB  exp(sim)*mask (tf32-rounded)
__device__ float g_Vt[(size_t)BB * DB * HB];     // 128 MB  hyp transposed [b,d,h], tf32-rounded
__device__ float g_Qr[(size_t)BB * PP * DB];     // 128 MB  premise tf32-rounded
__device__ float g_Kr[(size_t)BB * HB * DB];     // 128 MB  hyp tf32-rounded
__device__ float g_psum[(size_t)BB * PP * 16];   // per-(row, h-tile) partial sums
__device__ float g_rowsum[(size_t)BB * PP];

// ---- helpers ----
__device__ __forceinline__ float to_tf32(float x) {
    uint32_t u;
    asm("cvt.rna.tf32.f32 %0, %1;" : "=r"(u) : "f"(x));
    return __uint_as_float(u);
}

__device__ __forceinline__ uint32_t smem_u32(const void* p) {
    uint32_t a;
    asm("{ .reg .u64 t; cvta.to.shared.u64 t, %1; cvt.u32.u64 %0, t; }" : "=r"(a) : "l"(p));
    return a;
}

__device__ __forceinline__ void cp_async16(uint32_t dst, const void* src) {
    asm volatile("cp.async.cg.shared.global [%0], [%1], 16;" :: "r"(dst), "l"(src));
}

__device__ __forceinline__ void mma8(float c[4], float a0, float a1, float a2, float a3,
                                     float b0, float b1) {
    asm volatile(
        "mma.sync.aligned.m16n8k8.row.col.f32.tf32.tf32.f32 "
        "{%0,%1,%2,%3}, {%4,%5,%6,%7}, {%8,%9}, {%0,%1,%2,%3};\n"
        : "+f"(c[0]), "+f"(c[1]), "+f"(c[2]), "+f"(c[3])
        : "r"(__float_as_uint(a0)), "r"(__float_as_uint(a1)),
          "r"(__float_as_uint(a2)), "r"(__float_as_uint(a3)),
          "r"(__float_as_uint(b0)), "r"(__float_as_uint(b1)));
}

// ---------------------------------------------------------------------------
// prep kernels: tf32-round Q; round hypothesis into g_Kr and transposed g_Vt.
// ---------------------------------------------------------------------------
__global__ __launch_bounds__(256) void round_premise(const float4* __restrict__ in) {
    float4* outp = (float4*)g_Qr;
    const int n4 = BB * PP * DB / 4;
    int i = blockIdx.x * 256 + threadIdx.x;
    const int stride = gridDim.x * 256;
    for (; i < n4; i += stride) {
        float4 v = in[i];
        v.x = to_tf32(v.x); v.y = to_tf32(v.y); v.z = to_tf32(v.z); v.w = to_tf32(v.w);
        outp[i] = v;
    }
}

__global__ void prep_hyp(const float* __restrict__ hyp) {
    __shared__ float t[32][33];
    const int b = blockIdx.z;
    const int h0 = blockIdx.x * 32, d0 = blockIdx.y * 32;
    const int tx = threadIdx.x, ty = threadIdx.y;   // (32, 8)
#pragma unroll
    for (int i = 0; i < 4; i++) {
        int h = ty + i * 8;
        size_t idx = ((size_t)b * HB + h0 + h) * DB + d0 + tx;
        float v = to_tf32(hyp[idx]);
        g_Kr[idx] = v;
        t[tx][h] = v;
    }
    __syncthreads();
#pragma unroll
    for (int i = 0; i < 4; i++) {
        int d = ty + i * 8;
        g_Vt[((size_t)b * DB + d0 + d) * HB + h0 + tx] = t[d][tx];
    }
}

__global__ void rowsum_k() {
    int i = blockIdx.x * 256 + threadIdx.x;
    if (i < BB * PP) {
        float s = 0.0f;
#pragma unroll
        for (int j = 0; j < 16; j++) s += g_psum[(size_t)i * 16 + j];
        g_rowsum[i] = s;
    }
}

// ---------------------------------------------------------------------------
// tf32 mma.sync GEMM, CTA tile 128x128, 8 warps (2x4) of 64x32.
// cp.async double-buffered k32 chunks; LDS.128 fragment loads via k-relabel.
// Smem row stride = 48 words (192B): conflict-free LDS.128 phases.
// MODE 0: A=g_Qr, B=g_Kr (K=1024). Epilogue: E=exp(acc/32)*hmask -> g_E, psum.
// MODE 1: A=g_E,  B=g_Vt (K=2048). Epilogue: out = acc * pmask / rowsum.
// ---------------------------------------------------------------------------
#define STAGE_F 12288            // floats per stage (A 6144 + B 6144)
#define SMEM_BYTES (2 * STAGE_F * 4)   // 98304

template <int MODE>
__global__ __launch_bounds__(256, 2) void attn_gemm(const float* __restrict__ hmask,
                                                    const float* __restrict__ pmask,
                                                    float* __restrict__ outp) {
    constexpr int KD = MODE ? HB : DB;
    constexpr int S = KD / 32;

    extern __shared__ float sm[];
    const uint32_t sbase = smem_u32(sm);

    const int tid = threadIdx.x;
    const int x = blockIdx.x, y = blockIdx.y, b = blockIdx.z;
    const int lane = tid & 31, w = tid >> 5;
    const int wm = w >> 2, wn = w & 3;
    const int g = lane >> 2, tg = lane & 3;

    const float* Ab = (MODE ? g_E : g_Qr) + ((size_t)b * PP + (size_t)y * 128) * KD;
    const float* Bb = (MODE ? g_Vt : g_Kr) + (size_t)b * (size_t)(2048 * 1024)
                      + (size_t)x * 128 * KD;

    float acc[4][4][4];
#pragma unroll
    for (int mt = 0; mt < 4; mt++)
#pragma unroll
        for (int nt = 0; nt < 4; nt++)
#pragma unroll
            for (int i = 0; i < 4; i++) acc[mt][nt][i] = 0.0f;

    // per-thread cp.async coordinates: 4 A-chunks + 4 B-chunks of 16B
    const int cr[4] = { (0 * 256 + tid) >> 3, (1 * 256 + tid) >> 3,
                        (2 * 256 + tid) >> 3, (3 * 256 + tid) >> 3 };
    const int cc = tid & 7;

    auto load_stage = [&](int s, int buf) {
        if (s < S) {
            const int kc = s * 32;
            const uint32_t stb = sbase + (uint32_t)buf * (STAGE_F * 4);
#pragma unroll
            for (int i = 0; i < 4; i++) {
                uint32_t d = stb + (uint32_t)cr[i] * 192 + (uint32_t)cc * 16;
                cp_async16(d, Ab + (size_t)cr[i] * KD + kc + cc * 4);
                cp_async16(d + 24576, Bb + (size_t)cr[i] * KD + kc + cc * 4);
            }
        }
        asm volatile("cp.async.commit_group;" ::: "memory");
    };

    load_stage(0, 0);
    load_stage(1, 1);

    const int aoff = (wm * 64 + g) * 48 + 4 * tg;
    const int boff = 6144 + (wn * 32 + g) * 48 + 4 * tg;

#pragma unroll 1
    for (int s = 0; s < S; s++) {
        const int buf = s & 1;
        asm volatile("cp.async.wait_group 1;" ::: "memory");
        __syncthreads();

        const float* Aw = sm + buf * STAGE_F + aoff;
        const float* Bw = sm + buf * STAGE_F + boff;
#pragma unroll
        for (int j = 0; j < 2; j++) {
            float4 bf[4];
#pragma unroll
            for (int nt = 0; nt < 4; nt++)
                bf[nt] = *(const float4*)(Bw + nt * 8 * 48 + j * 16);
#pragma unroll
            for (int mt = 0; mt < 4; mt++) {
                float4 f0 = *(const float4*)(Aw + mt * 16 * 48 + j * 16);
                float4 f1 = *(const float4*)(Aw + mt * 16 * 48 + 8 * 48 + j * 16);
#pragma unroll
                for (int nt = 0; nt < 4; nt++) {
                    mma8(acc[mt][nt], f0.x, f1.x, f0.y, f1.y, bf[nt].x, bf[nt].y);
                    mma8(acc[mt][nt], f0.z, f1.z, f0.w, f1.w, bf[nt].z, bf[nt].w);
                }
            }
        }
        __syncthreads();
        load_stage(s + 2, buf);
    }

    // ---- epilogue ----
    __syncthreads();   // stage smem free for reuse
    const size_t growbase = (size_t)b * PP + (size_t)y * 128;

    if (MODE == 0) {
        const float* hm = hmask + (size_t)b * HB + x * 128;
        float ps[4][2];
#pragma unroll
        for (int mt = 0; mt < 4; mt++) { ps[mt][0] = 0.0f; ps[mt][1] = 0.0f; }

#pragma unroll
        for (int mt = 0; mt < 4; mt++) {
            const int r0 = wm * 64 + mt * 16 + g;
#pragma unroll
            for (int nt = 0; nt < 4; nt++) {
                const int col = wn * 32 + nt * 8 + 2 * tg;
                float2 m = *(const float2*)(hm + col);
                float e0 = (m.x != 0.0f) ? to_tf32(__expf(acc[mt][nt][0] * 0.03125f)) : 0.0f;
                float e1 = (m.y != 0.0f) ? to_tf32(__expf(acc[mt][nt][1] * 0.03125f)) : 0.0f;
                float e2 = (m.x != 0.0f) ? to_tf32(__expf(acc[mt][nt][2] * 0.03125f)) : 0.0f;
                float e3 = (m.y != 0.0f) ? to_tf32(__expf(acc[mt][nt][3] * 0.03125f)) : 0.0f;
                *(float2*)(g_E + (growbase + r0) * HB + x * 128 + col) = make_float2(e0, e1);
                *(float2*)(g_E + (growbase + r0 + 8) * HB + x * 128 + col) = make_float2(e2, e3);
                ps[mt][0] += e0 + e1;
                ps[mt][1] += e2 + e3;
            }
        }
        // reduce partial row sums across tg lanes, stash per-wn in smem
#pragma unroll
        for (int mt = 0; mt < 4; mt++)
#pragma unroll
            for (int h = 0; h < 2; h++) {
                float v = ps[mt][h];
                v += __shfl_xor_sync(0xFFFFFFFFu, v, 1);
                v += __shfl_xor_sync(0xFFFFFFFFu, v, 2);
                if (tg == 0) {
                    int rloc = wm * 64 + mt * 16 + g + h * 8;
                    sm[rloc * 4 + wn] = v;
                }
            }
        __syncthreads();
        if (tid < 128) {
            float s4 = sm[tid * 4 + 0] + sm[tid * 4 + 1] + sm[tid * 4 + 2] + sm[tid * 4 + 3];
            g_psum[(growbase + tid) * 16 + x] = s4;
        }
    } else {
#pragma unroll
        for (int mt = 0; mt < 4; mt++) {
            const int r0 = wm * 64 + mt * 16 + g;
            const size_t grow0 = growbase + r0, grow1 = growbase + r0 + 8;
            const float s0 = pmask[grow0] / (g_rowsum[grow0] + 1e-13f);
            const float s1 = pmask[grow1] / (g_rowsum[grow1] + 1e-13f);
#pragma unroll
            for (int nt = 0; nt < 4; nt++) {
                const int col = x * 128 + wn * 32 + nt * 8 + 2 * tg;
                *(float2*)(outp + grow0 * DB + col) =
                    make_float2(acc[mt][nt][0] * s0, acc[mt][nt][1] * s0);
                *(float2*)(outp + grow1 * DB + col) =
                    make_float2(acc[mt][nt][2] * s1, acc[mt][nt][3] * s1);
            }
        }
    }
}

// ---------------------------------------------------------------------------
extern "C" void kernel_launch(void* const* d_in, const int* in_sizes, int n_in,
                              void* d_out, int out_size) {
    const float* Q     = (const float*)d_in[0];  // premise_batch    [B,P,D]
    const float* pmask = (const float*)d_in[1];  // premise_mask     [B,P]
    const float* HYP   = (const float*)d_in[2];  // hypothesis_batch [B,H,D]
    const float* hmask = (const float*)d_in[3];  // hypothesis_mask  [B,H]
    float* out = (float*)d_out;

    cudaFuncSetAttribute(attn_gemm<0>, cudaFuncAttributeMaxDynamicSharedMemorySize, SMEM_BYTES);
    cudaFuncSetAttribute(attn_gemm<1>, cudaFuncAttributeMaxDynamicSharedMemorySize, SMEM_BYTES);

    round_premise<<<4096, 256>>>((const float4*)Q);
    prep_hyp<<<dim3(HB / 32, DB / 32, BB), dim3(32, 8)>>>(HYP);
    attn_gemm<0><<<dim3(16, 16, 16), 256, SMEM_BYTES>>>(hmask, nullptr, nullptr);
    rowsum_k<<<BB * PP / 256, 256>>>();
    attn_gemm<1><<<dim3(8, 16, 16), 256, SMEM_BYTES>>>(nullptr, pmask, out);
}

// round 5
// speedup vs baseline: 3.5492x; 1.8225x over previous
#include <cuda_runtime.h>
#include <cuda_fp16.h>
#include <cstdint>

#define BB 16
#define PP 2048
#define HB 2048
#define DB 1024

// ---- device scratch (static __device__ globals) ----
__device__ __half g_Eh[(size_t)BB * PP * HB];    // 128 MB  exp(sim)*mask, fp16
__device__ __half g_Qh[(size_t)BB * PP * DB];    //  64 MB  premise fp16
__device__ __half g_Kh[(size_t)BB * HB * DB];    //  64 MB  hypothesis fp16 [b,h,d]
__device__ __half g_Vth[(size_t)BB * DB * HB];   //  64 MB  hypothesis transposed [b,d,h] fp16
__device__ float g_psum[(size_t)BB * PP * 16];
__device__ float g_rowsum[(size_t)BB * PP];

// ---- helpers ----
__device__ __forceinline__ uint32_t smem_u32(const void* p) {
    uint32_t a;
    asm("{ .reg .u64 t; cvta.to.shared.u64 t, %1; cvt.u32.u64 %0, t; }" : "=r"(a) : "l"(p));
    return a;
}

__device__ __forceinline__ void cp_async16(uint32_t dst, const void* src) {
    asm volatile("cp.async.cg.shared.global [%0], [%1], 16;" :: "r"(dst), "l"(src));
}

__device__ __forceinline__ void ldsm4(uint32_t& r0, uint32_t& r1, uint32_t& r2, uint32_t& r3,
                                      uint32_t addr) {
    asm volatile("ldmatrix.sync.aligned.m8n8.x4.shared.b16 {%0,%1,%2,%3}, [%4];"
                 : "=r"(r0), "=r"(r1), "=r"(r2), "=r"(r3) : "r"(addr));
}

__device__ __forceinline__ void mma16(float c[4], uint32_t a0, uint32_t a1, uint32_t a2,
                                      uint32_t a3, uint32_t b0, uint32_t b1) {
    asm volatile(
        "mma.sync.aligned.m16n8k16.row.col.f32.f16.f16.f32 "
        "{%0,%1,%2,%3}, {%4,%5,%6,%7}, {%8,%9}, {%0,%1,%2,%3};\n"
        : "+f"(c[0]), "+f"(c[1]), "+f"(c[2]), "+f"(c[3])
        : "r"(a0), "r"(a1), "r"(a2), "r"(a3), "r"(b0), "r"(b1));
}

// ---------------------------------------------------------------------------
// prep: convert premise -> g_Qh; hypothesis -> g_Kh and transposed g_Vth.
// ---------------------------------------------------------------------------
__global__ __launch_bounds__(256) void conv_premise(const float4* __restrict__ in) {
    uint2* outp = (uint2*)g_Qh;
    const int n4 = BB * PP * DB / 4;
    int i = blockIdx.x * 256 + threadIdx.x;
    const int stride = gridDim.x * 256;
    for (; i < n4; i += stride) {
        float4 v = in[i];
        __half2 lo = __floats2half2_rn(v.x, v.y);
        __half2 hi = __floats2half2_rn(v.z, v.w);
        uint2 o;
        o.x = *reinterpret_cast<uint32_t*>(&lo);
        o.y = *reinterpret_cast<uint32_t*>(&hi);
        outp[i] = o;
    }
}

__global__ void prep_hyp(const float* __restrict__ hyp) {
    __shared__ float t[32][33];
    const int b = blockIdx.z;
    const int h0 = blockIdx.x * 32, d0 = blockIdx.y * 32;
    const int tx = threadIdx.x, ty = threadIdx.y;   // (32, 8)
#pragma unroll
    for (int i = 0; i < 4; i++) {
        int h = ty + i * 8;
        size_t idx = ((size_t)b * HB + h0 + h) * DB + d0 + tx;
        float v = hyp[idx];
        g_Kh[idx] = __float2half_rn(v);
        t[tx][h] = v;
    }
    __syncthreads();
#pragma unroll
    for (int i = 0; i < 4; i++) {
        int d = ty + i * 8;
        g_Vth[((size_t)b * DB + d0 + d) * HB + h0 + tx] = __float2half_rn(t[d][tx]);
    }
}

__global__ void rowsum_k() {
    int i = blockIdx.x * 256 + threadIdx.x;
    if (i < BB * PP) {
        float s = 0.0f;
#pragma unroll
        for (int j = 0; j < 16; j++) s += g_psum[(size_t)i * 16 + j];
        g_rowsum[i] = s;
    }
}

// ---------------------------------------------------------------------------
// fp16 mma.sync GEMM. CTA tile 128x128, 8 warps (2x4) of 64x32.
// k-chunks of 32 halfs; smem rows padded to 40 halfs (80B).
// 4-stage cp.async pipeline, one barrier per chunk; ldmatrix.x4 fragments.
// MODE 0: A=g_Qh, B=g_Kh (K=1024). Epilogue: E=exp(acc/32)*hmask -> g_Eh, psum.
// MODE 1: A=g_Eh, B=g_Vth (K=2048). Epilogue: out = acc * pmask / rowsum.
// ---------------------------------------------------------------------------
#define STAGE_B 20480u            // bytes per stage: (128 rows * 80B) * 2 operands
#define NSTAGE 4
#define SMEM_BYTES (NSTAGE * STAGE_B)   // 81920

template <int MODE>
__global__ __launch_bounds__(256, 2) void attn_gemm(const float* __restrict__ hmask,
                                                    const float* __restrict__ pmask,
                                                    float* __restrict__ outp) {
    constexpr int KD = MODE ? HB : DB;       // k extent in halfs
    constexpr int S = KD / 32;

    extern __shared__ float smf[];
    const uint32_t sbase = smem_u32(smf);

    const int tid = threadIdx.x;
    const int x = blockIdx.x, y = blockIdx.y, b = blockIdx.z;
    const int lane = tid & 31, w = tid >> 5;
    const int wm = w >> 2, wn = w & 3;
    const int g = lane >> 2, tg = lane & 3;

    // A batch stride is PP rows of length KD in BOTH modes (g_Qh: PP*DB, g_Eh: PP*HB).
    const __half* Ab = (MODE ? g_Eh : g_Qh) + ((size_t)b * PP + (size_t)y * 128) * KD;
    // B batch stride is 2M elements in both modes (g_Kh: HB*DB, g_Vth: DB*HB).
    const __half* Bb = (MODE ? g_Vth : g_Kh) + (size_t)b * (size_t)(HB * DB)
                       + (size_t)x * 128 * KD;

    float acc[4][4][4];
#pragma unroll
    for (int mt = 0; mt < 4; mt++)
#pragma unroll
        for (int nt = 0; nt < 4; nt++)
#pragma unroll
            for (int i = 0; i < 4; i++) acc[mt][nt][i] = 0.0f;

    // cp.async coords: per thread 2 A-chunks + 2 B-chunks of 16B (8 halfs)
    const int r0c = tid >> 2, r1c = (tid + 256) >> 2;
    const int cc = tid & 3;

    auto load_stage = [&](int s, int buf) {
        if (s < S) {
            const int kc = s * 32;
            const uint32_t stb = sbase + (uint32_t)buf * STAGE_B;
            uint32_t d0 = stb + (uint32_t)r0c * 80 + (uint32_t)cc * 16;
            uint32_t d1 = stb + (uint32_t)r1c * 80 + (uint32_t)cc * 16;
            cp_async16(d0, Ab + (size_t)r0c * KD + kc + cc * 8);
            cp_async16(d1, Ab + (size_t)r1c * KD + kc + cc * 8);
            cp_async16(d0 + STAGE_B / 2, Bb + (size_t)r0c * KD + kc + cc * 8);
            cp_async16(d1 + STAGE_B / 2, Bb + (size_t)r1c * KD + kc + cc * 8);
        }
        asm volatile("cp.async.commit_group;" ::: "memory");
    };

    load_stage(0, 0);
    load_stage(1, 1);
    load_stage(2, 2);

    // per-lane ldmatrix byte offsets
    const uint32_t a_off = (uint32_t)(wm * 64 + (lane & 15)) * 80 + (uint32_t)(lane >> 4) * 16;
    const uint32_t b_off = STAGE_B / 2 +
        (uint32_t)(wn * 32 + ((lane >> 4) << 3) + (lane & 7)) * 80 +
        (uint32_t)((lane >> 3) & 1) * 16;

#pragma unroll 1
    for (int s = 0; s < S; s++) {
        asm volatile("cp.async.wait_group 2;" ::: "memory");
        __syncthreads();
        load_stage(s + 3, (s + 3) & 3);

        const uint32_t stb = sbase + (uint32_t)(s & 3) * STAGE_B;
#pragma unroll
        for (int j = 0; j < 2; j++) {
            uint32_t bf[4][2];
#pragma unroll
            for (int ntp = 0; ntp < 2; ntp++) {
                uint32_t q0, q1, q2, q3;
                ldsm4(q0, q1, q2, q3, stb + b_off + (uint32_t)ntp * 1280 + (uint32_t)j * 32);
                bf[2 * ntp][0] = q0; bf[2 * ntp][1] = q1;
                bf[2 * ntp + 1][0] = q2; bf[2 * ntp + 1][1] = q3;
            }
#pragma unroll
            for (int mt = 0; mt < 4; mt++) {
                uint32_t a0, a1, a2, a3;
                ldsm4(a0, a1, a2, a3, stb + a_off + (uint32_t)mt * 1280 + (uint32_t)j * 32);
#pragma unroll
                for (int nt = 0; nt < 4; nt++)
                    mma16(acc[mt][nt], a0, a1, a2, a3, bf[nt][0], bf[nt][1]);
            }
        }
    }

    // ---- epilogue ----
    __syncthreads();
    const size_t growbase = (size_t)b * PP + (size_t)y * 128;

    if (MODE == 0) {
        const float* hm = hmask + (size_t)b * HB + x * 128;
        float ps[4][2];
#pragma unroll
        for (int mt = 0; mt < 4; mt++) { ps[mt][0] = 0.0f; ps[mt][1] = 0.0f; }

#pragma unroll
        for (int mt = 0; mt < 4; mt++) {
            const int r0 = wm * 64 + mt * 16 + g;
#pragma unroll
            for (int nt = 0; nt < 4; nt++) {
                const int col = wn * 32 + nt * 8 + 2 * tg;
                float2 m = *(const float2*)(hm + col);
                float e0 = (m.x != 0.0f) ? __expf(acc[mt][nt][0] * 0.03125f) : 0.0f;
                float e1 = (m.y != 0.0f) ? __expf(acc[mt][nt][1] * 0.03125f) : 0.0f;
                float e2 = (m.x != 0.0f) ? __expf(acc[mt][nt][2] * 0.03125f) : 0.0f;
                float e3 = (m.y != 0.0f) ? __expf(acc[mt][nt][3] * 0.03125f) : 0.0f;
                __half2 h01 = __floats2half2_rn(e0, e1);
                __half2 h23 = __floats2half2_rn(e2, e3);
                *(__half2*)(g_Eh + (growbase + r0) * HB + x * 128 + col) = h01;
                *(__half2*)(g_Eh + (growbase + r0 + 8) * HB + x * 128 + col) = h23;
                float2 f01 = __half22float2(h01);
                float2 f23 = __half22float2(h23);
                ps[mt][0] += f01.x + f01.y;
                ps[mt][1] += f23.x + f23.y;
            }
        }
#pragma unroll
        for (int mt = 0; mt < 4; mt++)
#pragma unroll
            for (int h = 0; h < 2; h++) {
                float v = ps[mt][h];
                v += __shfl_xor_sync(0xFFFFFFFFu, v, 1);
                v += __shfl_xor_sync(0xFFFFFFFFu, v, 2);
                if (tg == 0) {
                    int rloc = wm * 64 + mt * 16 + g + h * 8;
                    smf[rloc * 4 + wn] = v;
                }
            }
        __syncthreads();
        if (tid < 128) {
            float s4 = smf[tid * 4 + 0] + smf[tid * 4 + 1] + smf[tid * 4 + 2] + smf[tid * 4 + 3];
            g_psum[(growbase + tid) * 16 + x] = s4;
        }
    } else {
#pragma unroll
        for (int mt = 0; mt < 4; mt++) {
            const int r0 = wm * 64 + mt * 16 + g;
            const size_t grow0 = growbase + r0, grow1 = growbase + r0 + 8;
            const float s0 = pmask[grow0] / (g_rowsum[grow0] + 1e-13f);
            const float s1 = pmask[grow1] / (g_rowsum[grow1] + 1e-13f);
#pragma unroll
            for (int nt = 0; nt < 4; nt++) {
                const int col = x * 128 + wn * 32 + nt * 8 + 2 * tg;
                *(float2*)(outp + grow0 * DB + col) =
                    make_float2(acc[mt][nt][0] * s0, acc[mt][nt][1] * s0);
                *(float2*)(outp + grow1 * DB + col) =
                    make_float2(acc[mt][nt][2] * s1, acc[mt][nt][3] * s1);
            }
        }
    }
}

// ---------------------------------------------------------------------------
extern "C" void kernel_launch(void* const* d_in, const int* in_sizes, int n_in,
                              void* d_out, int out_size) {
    const float* Q     = (const float*)d_in[0];  // premise_batch    [B,P,D]
    const float* pmask = (const float*)d_in[1];  // premise_mask     [B,P]
    const float* HYP   = (const float*)d_in[2];  // hypothesis_batch [B,H,D]
    const float* hmask = (const float*)d_in[3];  // hypothesis_mask  [B,H]
    float* out = (float*)d_out;

    cudaFuncSetAttribute(attn_gemm<0>, cudaFuncAttributeMaxDynamicSharedMemorySize, SMEM_BYTES);
    cudaFuncSetAttribute(attn_gemm<1>, cudaFuncAttributeMaxDynamicSharedMemorySize, SMEM_BYTES);

    conv_premise<<<4096, 256>>>((const float4*)Q);
    prep_hyp<<<dim3(HB / 32, DB / 32, BB), dim3(32, 8)>>>(HYP);
    attn_gemm<0><<<dim3(16, 16, 16), 256, SMEM_BYTES>>>(hmask, nullptr, nullptr);
    rowsum_k<<<BB * PP / 256, 256>>>();
    attn_gemm<1><<<dim3(8, 16, 16), 256, SMEM_BYTES>>>(nullptr, pmask, out);
}

// round 6
// speedup vs baseline: 3.9323x; 1.1080x over previous
#include <cuda_runtime.h>
#include <cuda_fp16.h>
#include <cstdint>

#define BB 16
#define PP 2048
#define HB 2048
#define DB 1024

// ---- device scratch (static __device__ globals) ----
__device__ __half g_Eh[(size_t)BB * PP * HB];    // 128 MB  exp(sim)*mask, fp16
__device__ __half g_Qh[(size_t)BB * PP * DB];    //  64 MB  premise fp16
__device__ __half g_Kh[(size_t)BB * HB * DB];    //  64 MB  hypothesis fp16 [b,h,d]
__device__ __half g_Vth[(size_t)BB * DB * HB];   //  64 MB  hypothesis transposed [b,d,h] fp16
__device__ float g_psum[(size_t)BB * PP * 16];
__device__ float g_rowsum[(size_t)BB * PP];

// ---- helpers ----
__device__ __forceinline__ uint32_t smem_u32(const void* p) {
    uint32_t a;
    asm("{ .reg .u64 t; cvta.to.shared.u64 t, %1; cvt.u32.u64 %0, t; }" : "=r"(a) : "l"(p));
    return a;
}

__device__ __forceinline__ void cp_async16(uint32_t dst, const void* src) {
    asm volatile("cp.async.cg.shared.global [%0], [%1], 16;" :: "r"(dst), "l"(src));
}

__device__ __forceinline__ void ldsm4(uint32_t& r0, uint32_t& r1, uint32_t& r2, uint32_t& r3,
                                      uint32_t addr) {
    asm volatile("ldmatrix.sync.aligned.m8n8.x4.shared.b16 {%0,%1,%2,%3}, [%4];"
                 : "=r"(r0), "=r"(r1), "=r"(r2), "=r"(r3) : "r"(addr));
}

__device__ __forceinline__ void mma16(float c[4], uint32_t a0, uint32_t a1, uint32_t a2,
                                      uint32_t a3, uint32_t b0, uint32_t b1) {
    asm volatile(
        "mma.sync.aligned.m16n8k16.row.col.f32.f16.f16.f32 "
        "{%0,%1,%2,%3}, {%4,%5,%6,%7}, {%8,%9}, {%0,%1,%2,%3};\n"
        : "+f"(c[0]), "+f"(c[1]), "+f"(c[2]), "+f"(c[3])
        : "r"(a0), "r"(a1), "r"(a2), "r"(a3), "r"(b0), "r"(b1));
}

// ---------------------------------------------------------------------------
// prep kernels
// ---------------------------------------------------------------------------
__global__ __launch_bounds__(256) void conv_premise(const float4* __restrict__ in) {
    uint2* outp = (uint2*)g_Qh;
    const int n4 = BB * PP * DB / 4;
    int i = blockIdx.x * 256 + threadIdx.x;
    const int stride = gridDim.x * 256;
    for (; i < n4; i += stride) {
        float4 v = in[i];
        __half2 lo = __floats2half2_rn(v.x, v.y);
        __half2 hi = __floats2half2_rn(v.z, v.w);
        uint2 o;
        o.x = *reinterpret_cast<uint32_t*>(&lo);
        o.y = *reinterpret_cast<uint32_t*>(&hi);
        outp[i] = o;
    }
}

__global__ void prep_hyp(const float* __restrict__ hyp) {
    __shared__ float t[32][33];
    const int b = blockIdx.z;
    const int h0 = blockIdx.x * 32, d0 = blockIdx.y * 32;
    const int tx = threadIdx.x, ty = threadIdx.y;   // (32, 8)
#pragma unroll
    for (int i = 0; i < 4; i++) {
        int h = ty + i * 8;
        size_t idx = ((size_t)b * HB + h0 + h) * DB + d0 + tx;
        float v = hyp[idx];
        g_Kh[idx] = __float2half_rn(v);
        t[tx][h] = v;
    }
    __syncthreads();
#pragma unroll
    for (int i = 0; i < 4; i++) {
        int d = ty + i * 8;
        g_Vth[((size_t)b * DB + d0 + d) * HB + h0 + tx] = __float2half_rn(t[d][tx]);
    }
}

__global__ void rowsum_k() {
    int i = blockIdx.x * 256 + threadIdx.x;
    if (i < BB * PP) {
        float s = 0.0f;
#pragma unroll
        for (int j = 0; j < 16; j++) s += g_psum[(size_t)i * 16 + j];
        g_rowsum[i] = s;
    }
}

// ---------------------------------------------------------------------------
// fp16 mma.sync GEMM. CTA tile 128x128, 4 warps (2x2), warp tile 64x64.
// k-chunks of 32 halfs; smem rows padded to 40 halfs (80B).
// 4-stage cp.async pipeline, one barrier per chunk; ldmatrix.x4 fragments.
// MODE 0: A=g_Qh, B=g_Kh (K=1024). Epilogue: E=exp(acc/32)*hmask -> g_Eh, psum.
// MODE 1: A=g_Eh, B=g_Vth (K=2048). Epilogue: out = acc * pmask / rowsum.
// ---------------------------------------------------------------------------
#define STAGE_B 20480u            // bytes per stage: (256 rows * 80B)
#define NSTAGE 4
#define SMEM_BYTES (NSTAGE * STAGE_B)   // 81920

template <int MODE>
__global__ __launch_bounds__(128, 2) void attn_gemm(const float* __restrict__ hmask,
                                                    const float* __restrict__ pmask,
                                                    float* __restrict__ outp) {
    constexpr int KD = MODE ? HB : DB;       // k extent in halfs
    constexpr int S = KD / 32;

    extern __shared__ float smf[];
    const uint32_t sbase = smem_u32(smf);

    const int tid = threadIdx.x;
    const int x = blockIdx.x, y = blockIdx.y, b = blockIdx.z;
    const int lane = tid & 31, w = tid >> 5;
    const int wm = w >> 1, wn = w & 1;       // 2x2 warps, each 64x64
    const int g = lane >> 2, tg = lane & 3;

    // A batch stride = PP rows of KD in both modes; B batch stride = 2M elems.
    const __half* Ab = (MODE ? g_Eh : g_Qh) + ((size_t)b * PP + (size_t)y * 128) * KD;
    const __half* Bb = (MODE ? g_Vth : g_Kh) + (size_t)b * (size_t)(HB * DB)
                       + (size_t)x * 128 * KD;

    float acc[4][8][4];
#pragma unroll
    for (int mt = 0; mt < 4; mt++)
#pragma unroll
        for (int nt = 0; nt < 8; nt++)
#pragma unroll
            for (int i = 0; i < 4; i++) acc[mt][nt][i] = 0.0f;

    auto load_stage = [&](int s, int buf) {
        if (s < S) {
            const int kc = s * 32;
            const uint32_t stb = sbase + (uint32_t)buf * STAGE_B;
#pragma unroll
            for (int i = 0; i < 4; i++) {
                int idx = i * 128 + tid;          // 0..511
                int r = idx >> 2, c = idx & 3;
                uint32_t d = stb + (uint32_t)r * 80 + (uint32_t)c * 16;
                cp_async16(d, Ab + (size_t)r * KD + kc + c * 8);
                cp_async16(d + STAGE_B / 2, Bb + (size_t)r * KD + kc + c * 8);
            }
        }
        asm volatile("cp.async.commit_group;" ::: "memory");
    };

    load_stage(0, 0);
    load_stage(1, 1);
    load_stage(2, 2);

    // per-lane ldmatrix byte offsets
    const uint32_t a_off = (uint32_t)(wm * 64 + (lane & 15)) * 80 + (uint32_t)(lane >> 4) * 16;
    const uint32_t b_off = STAGE_B / 2 +
        (uint32_t)(wn * 64 + ((lane >> 4) << 3) + (lane & 7)) * 80 +
        (uint32_t)((lane >> 3) & 1) * 16;

#pragma unroll 1
    for (int s = 0; s < S; s++) {
        asm volatile("cp.async.wait_group 2;" ::: "memory");
        __syncthreads();
        load_stage(s + 3, (s + 3) & 3);

        const uint32_t stb = sbase + (uint32_t)(s & 3) * STAGE_B;
#pragma unroll
        for (int j = 0; j < 2; j++) {
            uint32_t bf[8][2];
#pragma unroll
            for (int ntp = 0; ntp < 4; ntp++) {
                uint32_t q0, q1, q2, q3;
                ldsm4(q0, q1, q2, q3, stb + b_off + (uint32_t)ntp * 1280 + (uint32_t)j * 32);
                bf[2 * ntp][0] = q0; bf[2 * ntp][1] = q1;
                bf[2 * ntp + 1][0] = q2; bf[2 * ntp + 1][1] = q3;
            }
#pragma unroll
            for (int mt = 0; mt < 4; mt++) {
                uint32_t a0, a1, a2, a3;
                ldsm4(a0, a1, a2, a3, stb + a_off + (uint32_t)mt * 1280 + (uint32_t)j * 32);
#pragma unroll
                for (int nt = 0; nt < 8; nt++)
                    mma16(acc[mt][nt], a0, a1, a2, a3, bf[nt][0], bf[nt][1]);
            }
        }
    }

    // ---- epilogue ----
    __syncthreads();
    const size_t growbase = (size_t)b * PP + (size_t)y * 128;

    if (MODE == 0) {
        const float* hm = hmask + (size_t)b * HB + x * 128;
        float ps[4][2];
#pragma unroll
        for (int mt = 0; mt < 4; mt++) { ps[mt][0] = 0.0f; ps[mt][1] = 0.0f; }

#pragma unroll
        for (int mt = 0; mt < 4; mt++) {
            const int r0 = wm * 64 + mt * 16 + g;
#pragma unroll
            for (int nt = 0; nt < 8; nt++) {
                const int col = wn * 64 + nt * 8 + 2 * tg;
                float2 m = *(const float2*)(hm + col);
                float e0 = (m.x != 0.0f) ? __expf(acc[mt][nt][0] * 0.03125f) : 0.0f;
                float e1 = (m.y != 0.0f) ? __expf(acc[mt][nt][1] * 0.03125f) : 0.0f;
                float e2 = (m.x != 0.0f) ? __expf(acc[mt][nt][2] * 0.03125f) : 0.0f;
                float e3 = (m.y != 0.0f) ? __expf(acc[mt][nt][3] * 0.03125f) : 0.0f;
                __half2 h01 = __floats2half2_rn(e0, e1);
                __half2 h23 = __floats2half2_rn(e2, e3);
                *(__half2*)(g_Eh + (growbase + r0) * HB + x * 128 + col) = h01;
                *(__half2*)(g_Eh + (growbase + r0 + 8) * HB + x * 128 + col) = h23;
                float2 f01 = __half22float2(h01);
                float2 f23 = __half22float2(h23);
                ps[mt][0] += f01.x + f01.y;
                ps[mt][1] += f23.x + f23.y;
            }
        }
#pragma unroll
        for (int mt = 0; mt < 4; mt++)
#pragma unroll
            for (int h = 0; h < 2; h++) {
                float v = ps[mt][h];
                v += __shfl_xor_sync(0xFFFFFFFFu, v, 1);
                v += __shfl_xor_sync(0xFFFFFFFFu, v, 2);
                if (tg == 0) {
                    int rloc = wm * 64 + mt * 16 + g + h * 8;
                    smf[rloc * 2 + wn] = v;
                }
            }
        __syncthreads();
        if (tid < 128) {
            float s2 = smf[tid * 2 + 0] + smf[tid * 2 + 1];
            g_psum[(growbase + tid) * 16 + x] = s2;
        }
    } else {
#pragma unroll
        for (int mt = 0; mt < 4; mt++) {
            const int r0 = wm * 64 + mt * 16 + g;
            const size_t grow0 = growbase + r0, grow1 = growbase + r0 + 8;
            const float s0 = pmask[grow0] / (g_rowsum[grow0] + 1e-13f);
            const float s1 = pmask[grow1] / (g_rowsum[grow1] + 1e-13f);
#pragma unroll
            for (int nt = 0; nt < 8; nt++) {
                const int col = x * 128 + wn * 64 + nt * 8 + 2 * tg;
                *(float2*)(outp + grow0 * DB + col) =
                    make_float2(acc[mt][nt][0] * s0, acc[mt][nt][1] * s0);
                *(float2*)(outp + grow1 * DB + col) =
                    make_float2(acc[mt][nt][2] * s1, acc[mt][nt][3] * s1);
            }
        }
    }
}

// ---------------------------------------------------------------------------
extern "C" void kernel_launch(void* const* d_in, const int* in_sizes, int n_in,
                              void* d_out, int out_size) {
    const float* Q     = (const float*)d_in[0];  // premise_batch    [B,P,D]
    const float* pmask = (const float*)d_in[1];  // premise_mask     [B,P]
    const float* HYP   = (const float*)d_in[2];  // hypothesis_batch [B,H,D]
    const float* hmask = (const float*)d_in[3];  // hypothesis_mask  [B,H]
    float* out = (float*)d_out;

    cudaFuncSetAttribute(attn_gemm<0>, cudaFuncAttributeMaxDynamicSharedMemorySize, SMEM_BYTES);
    cudaFuncSetAttribute(attn_gemm<1>, cudaFuncAttributeMaxDynamicSharedMemorySize, SMEM_BYTES);

    conv_premise<<<4096, 256>>>((const float4*)Q);
    prep_hyp<<<dim3(HB / 32, DB / 32, BB), dim3(32, 8)>>>(HYP);
    attn_gemm<0><<<dim3(16, 16, 16), 128, SMEM_BYTES>>>(hmask, nullptr, nullptr);
    rowsum_k<<<BB * PP / 256, 256>>>();
    attn_gemm<1><<<dim3(8, 16, 16), 128, SMEM_BYTES>>>(nullptr, pmask, out);
}